// round 4
// baseline (speedup 1.0000x reference)
#include <cuda_runtime.h>
#include <cuda_bf16.h>
#include <math.h>

#define BB 8
#define HH 256
#define LL 8192
#define NN 16
#define DTE 512
#define DI 512   // expand*H
#define O2 512   // 2*H

// ---------------- scratch (device globals; no allocation allowed) ----------
__device__ float  g_partt[BB*HH];
__device__ float2 g_stats[BB*LL];
__device__ float2 g_lam[HH*NN];
__device__ float2 g_c0[HH*NN];
__device__ float2 g_c1[HH*NN];
__device__ float  g_u [BB*HH*LL];   // u after LN1+part_t; later reused as yn (LN2 out)
__device__ float  g_yf[BB*HH*LL];   // fwd scan contrib; later y = gelu(yf+yb+u*D)
__device__ float  g_yb[BB*HH*LL];   // bwd scan contrib
__device__ float  g_z [BB*O2*LL];   // z (pre-GLU); later reused as h1 (FFN mid)
__device__ float  g_y1[BB*HH*LL];   // residual-1 output

// ---------------- helpers ---------------------------------------------------
__device__ __forceinline__ float gelu_t(float x) {
    float x3 = x * x * x;
    return 0.5f * x * (1.0f + tanhf(0.7978845608028654f * (x + 0.044715f * x3)));
}
__device__ __forceinline__ float sigm(float x) { return 1.0f / (1.0f + expf(-x)); }

// ---------------- setup: lambda and 2*C' coefficients -----------------------
__global__ void k_setup(const float* __restrict__ log_dt,
                        const float* __restrict__ A_re, const float* __restrict__ A_im,
                        const float* __restrict__ C_re, const float* __restrict__ C_im) {
    int h = blockIdx.x, n = threadIdx.x;
    int i = h * NN + n;
    float dt  = expf(log_dt[h]);
    float ar  = A_re[i] * dt, ai = A_im[i] * dt;    // dtA
    float e   = expf(ar);
    float lre = e * cosf(ai), lim = e * sinf(ai);   // lambda = exp(dtA)
    float Are = A_re[i], Aim = A_im[i];
    float den = Are * Are + Aim * Aim;
    float num_r = lre - 1.0f, num_i = lim;
    float fre = (num_r * Are + num_i * Aim) / den;  // (lambda-1)/A
    float fim = (num_i * Are - num_r * Aim) / den;
    float c0r = C_re[i], c0i = C_im[i];
    float c1r = C_re[HH*NN + i], c1i = C_im[HH*NN + i];
    g_lam[i] = make_float2(lre, lim);
    g_c0[i]  = make_float2(2.0f*(c0r*fre - c0i*fim), 2.0f*(c0r*fim + c0i*fre));
    g_c1[i]  = make_float2(2.0f*(c1r*fre - c1i*fim), 2.0f*(c1r*fim + c1i*fre));
}

// ---------------- part_t = emb @ fc_t_w^T + b -------------------------------
__global__ void k_partt(const float* __restrict__ emb, const float* __restrict__ w,
                        const float* __restrict__ bias) {
    int gw   = blockIdx.x * 8 + (threadIdx.x >> 5);  // warp id: one per (b,h)
    int lane = threadIdx.x & 31;
    int b = gw >> 8, h = gw & 255;
    float s = 0.f;
    #pragma unroll
    for (int k = lane; k < DTE; k += 32)
        s += emb[b*DTE + k] * w[h*DTE + k];
    #pragma unroll
    for (int o = 16; o > 0; o >>= 1) s += __shfl_xor_sync(0xffffffffu, s, o);
    if (lane == 0) g_partt[b*HH + h] = s + bias[h];
}

// ---------------- per-(b,l) mean/rstd over H --------------------------------
__global__ void k_stats(const float* __restrict__ inp) {
    int b = blockIdx.y;
    int l = blockIdx.x * 256 + threadIdx.x;
    const float* p = inp + (size_t)b * HH * LL + l;
    float s = 0.f, sq = 0.f;
    #pragma unroll 8
    for (int h = 0; h < HH; h++) {
        float v = p[(size_t)h * LL];
        s += v; sq += v * v;
    }
    float mean = s * (1.0f / HH);
    float var  = sq * (1.0f / HH) - mean * mean;
    float rstd = rsqrtf(fmaxf(var, 1e-20f));
    g_stats[b*LL + l] = make_float2(mean, rstd);
}

// ---------------- LN1 + part_t -> u -----------------------------------------
__global__ void k_norm1(const float* __restrict__ x,
                        const float* __restrict__ n_m, const float* __restrict__ n_s) {
    float m0 = *n_m, s0 = *n_s;
    size_t i4 = (size_t)blockIdx.x * 256 + threadIdx.x;
    size_t idx = i4 * 4;
    int l = (int)(idx & (LL - 1));
    int h = (int)((idx >> 13) & (HH - 1));
    int b = (int)(idx >> 21);
    float pt = g_partt[b*HH + h];
    float4 xv = *(const float4*)(x + idx);
    float4 o;
    float2 st;
    st = g_stats[b*LL + l + 0]; o.x = s0*st.y*(xv.x - st.x + m0) + pt;
    st = g_stats[b*LL + l + 1]; o.y = s0*st.y*(xv.y - st.x + m0) + pt;
    st = g_stats[b*LL + l + 2]; o.z = s0*st.y*(xv.z - st.x + m0) + pt;
    st = g_stats[b*LL + l + 3]; o.w = s0*st.y*(xv.w - st.x + m0) + pt;
    *(float4*)(g_u + idx) = o;
}

// ---------------- bidirectional diagonal SSM scan ---------------------------
// warp = 2 heads x 16 modes/lane; gridDim.y selects direction.
__global__ void k_scan() {
    int warp = threadIdx.x >> 5, lane = threadIdx.x & 31;
    int pair = blockIdx.x * 4 + warp;          // 0..1023
    int sub  = lane >> 4, n = lane & 15;
    int bh   = pair * 2 + sub;                 // 0..2047
    int h    = bh & 255;
    int dir  = blockIdx.y;
    float2 lam = g_lam[h*NN + n];
    float2 c   = (dir == 0 ? g_c0 : g_c1)[h*NN + n];
    const float* u = g_u + (size_t)bh * LL;
    float* out = (dir == 0 ? g_yf : g_yb) + (size_t)bh * LL;
    float sr = 0.f, si = 0.f;
    if (dir == 0) {
        for (int l = 0; l < LL; l += 4) {
            float4 uv = *(const float4*)(u + l);
            float y0, y1, y2, y3, nr;
            nr = fmaf(lam.x, sr, fmaf(-lam.y, si, uv.x)); si = fmaf(lam.x, si, lam.y*sr); sr = nr;
            y0 = c.x*sr - c.y*si;
            nr = fmaf(lam.x, sr, fmaf(-lam.y, si, uv.y)); si = fmaf(lam.x, si, lam.y*sr); sr = nr;
            y1 = c.x*sr - c.y*si;
            nr = fmaf(lam.x, sr, fmaf(-lam.y, si, uv.z)); si = fmaf(lam.x, si, lam.y*sr); sr = nr;
            y2 = c.x*sr - c.y*si;
            nr = fmaf(lam.x, sr, fmaf(-lam.y, si, uv.w)); si = fmaf(lam.x, si, lam.y*sr); sr = nr;
            y3 = c.x*sr - c.y*si;
            #pragma unroll
            for (int o = 8; o > 0; o >>= 1) {
                y0 += __shfl_xor_sync(0xffffffffu, y0, o);
                y1 += __shfl_xor_sync(0xffffffffu, y1, o);
                y2 += __shfl_xor_sync(0xffffffffu, y2, o);
                y3 += __shfl_xor_sync(0xffffffffu, y3, o);
            }
            if (n == 0) *(float4*)(out + l) = make_float4(y0, y1, y2, y3);
        }
    } else {
        // t[l] = u[l+1] + lam*t[l+1]; y[l] = 2Re(c1' t[l])
        for (int l = LL - 1; l >= 3; l -= 4) {
            float4 uv = *(const float4*)(u + l - 3);   // u[l-3..l]
            float y0, y1, y2, y3, nr;
            y0 = c.x*sr - c.y*si;   // at l
            nr = fmaf(lam.x, sr, fmaf(-lam.y, si, uv.w)); si = fmaf(lam.x, si, lam.y*sr); sr = nr;
            y1 = c.x*sr - c.y*si;   // at l-1
            nr = fmaf(lam.x, sr, fmaf(-lam.y, si, uv.z)); si = fmaf(lam.x, si, lam.y*sr); sr = nr;
            y2 = c.x*sr - c.y*si;   // at l-2
            nr = fmaf(lam.x, sr, fmaf(-lam.y, si, uv.y)); si = fmaf(lam.x, si, lam.y*sr); sr = nr;
            y3 = c.x*sr - c.y*si;   // at l-3
            nr = fmaf(lam.x, sr, fmaf(-lam.y, si, uv.x)); si = fmaf(lam.x, si, lam.y*sr); sr = nr;
            #pragma unroll
            for (int o = 8; o > 0; o >>= 1) {
                y0 += __shfl_xor_sync(0xffffffffu, y0, o);
                y1 += __shfl_xor_sync(0xffffffffu, y1, o);
                y2 += __shfl_xor_sync(0xffffffffu, y2, o);
                y3 += __shfl_xor_sync(0xffffffffu, y3, o);
            }
            if (n == 0) *(float4*)(out + l - 3) = make_float4(y3, y2, y1, y0);
        }
    }
}

// ---------------- combine: y = gelu(yf + yb + u*D) -> g_yf ------------------
__global__ void k_combine(const float* __restrict__ D) {
    size_t i4 = (size_t)blockIdx.x * 256 + threadIdx.x;
    size_t idx = i4 * 4;
    int h = (int)((idx >> 13) & (HH - 1));
    float d = D[h];
    float4 a = *(const float4*)(g_yf + idx);
    float4 bv = *(const float4*)(g_yb + idx);
    float4 uv = *(const float4*)(g_u + idx);
    float4 o;
    o.x = gelu_t(a.x + bv.x + uv.x * d);
    o.y = gelu_t(a.y + bv.y + uv.y * d);
    o.z = gelu_t(a.z + bv.z + uv.z * d);
    o.w = gelu_t(a.w + bv.w + uv.w * d);
    *(float4*)(g_yf + idx) = o;
}

// ---------------- GLU + residual: y1 = x + z1*sigmoid(z2) -------------------
__global__ void k_glu(const float* __restrict__ x, const float* __restrict__ out_b) {
    size_t i4 = (size_t)blockIdx.x * 256 + threadIdx.x;
    size_t idx = i4 * 4;
    int l = (int)(idx & (LL - 1));
    int h = (int)((idx >> 13) & (HH - 1));
    int b = (int)(idx >> 21);
    float b1 = out_b[h], b2 = out_b[h + HH];
    const float* z1 = g_z + ((size_t)b * O2 + h) * LL + l;
    const float* z2 = g_z + ((size_t)b * O2 + h + HH) * LL + l;
    float4 a = *(const float4*)z1;
    float4 g = *(const float4*)z2;
    float4 xv = *(const float4*)(x + idx);
    float4 o;
    o.x = xv.x + (a.x + b1) * sigm(g.x + b2);
    o.y = xv.y + (a.y + b1) * sigm(g.y + b2);
    o.z = xv.z + (a.z + b1) * sigm(g.z + b2);
    o.w = xv.w + (a.w + b1) * sigm(g.w + b2);
    *(float4*)(g_y1 + idx) = o;
}

// ---------------- LN2 -> yn (into g_u) --------------------------------------
__global__ void k_norm2(const float* __restrict__ n_m, const float* __restrict__ n_s) {
    float m0 = *n_m, s0 = *n_s;
    size_t i4 = (size_t)blockIdx.x * 256 + threadIdx.x;
    size_t idx = i4 * 4;
    int l = (int)(idx & (LL - 1));
    int b = (int)(idx >> 21);
    float4 xv = *(const float4*)(g_y1 + idx);
    float4 o;
    float2 st;
    st = g_stats[b*LL + l + 0]; o.x = s0*st.y*(xv.x - st.x + m0);
    st = g_stats[b*LL + l + 1]; o.y = s0*st.y*(xv.y - st.x + m0);
    st = g_stats[b*LL + l + 2]; o.z = s0*st.y*(xv.z - st.x + m0);
    st = g_stats[b*LL + l + 3]; o.w = s0*st.y*(xv.w - st.x + m0);
    *(float4*)(g_u + idx) = o;
}

// ---------------- SGEMM: C[b,m,l] = sum_k A[m,k] * Bm[b,k,l] ----------------
// EPI 0: plain.  EPI 1: gelu(v+bias[m]).  EPI 2: v+bias[m]+res[b,m,l].
#define BM 128
#define BN 128
#define BK 8
template <int EPI>
__global__ void __launch_bounds__(256, 2)
gemm_kernel(const float* __restrict__ A, const float* __restrict__ Bm,
            float* __restrict__ C, const float* __restrict__ bias,
            const float* __restrict__ res, int M, int K) {
    __shared__ float As[BK][BM];
    __shared__ float Bs[BK][BN];
    int b = blockIdx.z;
    const float* Bp = Bm + (size_t)b * K * LL;
    float*       Cp = C  + (size_t)b * M * LL;
    const float* Rp = (EPI == 2) ? (res + (size_t)b * M * LL) : nullptr;

    int tid = threadIdx.x;
    int m0 = blockIdx.y * BM, n0 = blockIdx.x * BN;
    int a_row = tid >> 1,  a_col = (tid & 1) * 4;
    int b_row = tid >> 5,  b_col = (tid & 31) * 4;
    int ty = tid >> 4, tx = tid & 15;

    float acc[8][8];
    #pragma unroll
    for (int i = 0; i < 8; i++)
        #pragma unroll
        for (int j = 0; j < 8; j++) acc[i][j] = 0.f;

    for (int k0 = 0; k0 < K; k0 += BK) {
        float4 av = *(const float4*)(A + (size_t)(m0 + a_row) * K + k0 + a_col);
        As[a_col + 0][a_row] = av.x;
        As[a_col + 1][a_row] = av.y;
        As[a_col + 2][a_row] = av.z;
        As[a_col + 3][a_row] = av.w;
        *(float4*)&Bs[b_row][b_col] =
            *(const float4*)(Bp + (size_t)(k0 + b_row) * LL + n0 + b_col);
        __syncthreads();
        #pragma unroll
        for (int k = 0; k < BK; k++) {
            float ar[8], br[8];
            *(float4*)&ar[0] = *(const float4*)&As[k][ty * 8];
            *(float4*)&ar[4] = *(const float4*)&As[k][ty * 8 + 4];
            *(float4*)&br[0] = *(const float4*)&Bs[k][tx * 8];
            *(float4*)&br[4] = *(const float4*)&Bs[k][tx * 8 + 4];
            #pragma unroll
            for (int i = 0; i < 8; i++)
                #pragma unroll
                for (int j = 0; j < 8; j++)
                    acc[i][j] = fmaf(ar[i], br[j], acc[i][j]);
        }
        __syncthreads();
    }

    #pragma unroll
    for (int i = 0; i < 8; i++) {
        int m = m0 + ty * 8 + i;
        size_t rowoff = (size_t)m * LL + n0 + tx * 8;
        float bs = (EPI != 0) ? bias[m] : 0.f;
        float v[8];
        #pragma unroll
        for (int j = 0; j < 8; j++) {
            float t = acc[i][j];
            if (EPI == 1) t = gelu_t(t + bs);
            if (EPI == 2) t = t + bs + Rp[rowoff + j];
            v[j] = t;
        }
        *(float4*)(Cp + rowoff)     = make_float4(v[0], v[1], v[2], v[3]);
        *(float4*)(Cp + rowoff + 4) = make_float4(v[4], v[5], v[6], v[7]);
    }
}

// ---------------- launch ----------------------------------------------------
extern "C" void kernel_launch(void* const* d_in, const int* in_sizes, int n_in,
                              void* d_out, int out_size) {
    const float* x      = (const float*)d_in[0];
    const float* emb    = (const float*)d_in[1];
    const float* fc_t_w = (const float*)d_in[2];
    const float* fc_t_b = (const float*)d_in[3];
    const float* log_dt = (const float*)d_in[4];
    const float* A_re   = (const float*)d_in[5];
    const float* A_im   = (const float*)d_in[6];
    const float* C_re   = (const float*)d_in[7];
    const float* C_im   = (const float*)d_in[8];
    const float* Dp     = (const float*)d_in[9];
    const float* out_w  = (const float*)d_in[10];
    const float* out_b  = (const float*)d_in[11];
    const float* n1_m   = (const float*)d_in[12];
    const float* n1_s   = (const float*)d_in[13];
    const float* n2_m   = (const float*)d_in[14];
    const float* n2_s   = (const float*)d_in[15];
    const float* ff_w1  = (const float*)d_in[16];
    const float* ff_b1  = (const float*)d_in[17];
    const float* ff_w2  = (const float*)d_in[18];
    const float* ff_b2  = (const float*)d_in[19];
    float* out = (float*)d_out;

    float *p_yf, *p_z, *p_u, *p_y1;
    cudaGetSymbolAddress((void**)&p_yf, g_yf);
    cudaGetSymbolAddress((void**)&p_z,  g_z);
    cudaGetSymbolAddress((void**)&p_u,  g_u);
    cudaGetSymbolAddress((void**)&p_y1, g_y1);

    const int EW_BLOCKS = (BB * HH * LL) / (256 * 4);  // 16384

    k_setup<<<HH, NN>>>(log_dt, A_re, A_im, C_re, C_im);
    k_partt<<<(BB * HH) / 8, 256>>>(emb, fc_t_w, fc_t_b);
    k_stats<<<dim3(LL / 256, BB), 256>>>(x);
    k_norm1<<<EW_BLOCKS, 256>>>(x, n1_m, n1_s);
    k_scan<<<dim3((BB * HH) / 8, 2), 128>>>();
    k_combine<<<EW_BLOCKS, 256>>>(Dp);
    // z = out_w @ y
    gemm_kernel<0><<<dim3(LL / BN, O2 / BM, BB), 256>>>(out_w, p_yf, p_z,
                                                        nullptr, nullptr, O2, HH);
    k_glu<<<EW_BLOCKS, 256>>>(x, out_b);
    k_stats<<<dim3(LL / 256, BB), 256>>>(p_y1);
    k_norm2<<<EW_BLOCKS, 256>>>(n2_m, n2_s);
    // h1 = gelu(ff_w1 @ yn + b1)  (yn in g_u, h1 overwrites g_z)
    gemm_kernel<1><<<dim3(LL / BN, DI / BM, BB), 256>>>(ff_w1, p_u, p_z,
                                                        ff_b1, nullptr, DI, HH);
    // out = y1 + ff_w2 @ h1 + b2
    gemm_kernel<2><<<dim3(LL / BN, HH / BM, BB), 256>>>(ff_w2, p_z, out,
                                                        ff_b2, p_y1, HH, DI);
}